// round 1
// baseline (speedup 1.0000x reference)
#include <cuda_runtime.h>
#include <cuda_bf16.h>
#include <stdint.h>

#define N_SAMPLES 32768
#define N_ATOMS   2048
#define ATOM_SIZE 1024
#define K_SPARSE  64
#define BATCH     4
#define PADN      33824   // 512 pad + 32768 + 512 pad + 32 slack (zeroed)
#define CAP       65536

// ---------------- device scratch (static, allocation-free) ----------------
__device__ __nv_bfloat16 g_origpad_bf[BATCH * PADN];
__device__ float         g_origpad_f [BATCH * PADN];
__device__ __nv_bfloat16 g_atoms_bf  [N_ATOMS * ATOM_SIZE];
__device__ unsigned      g_cnt[BATCH];
__device__ unsigned      g_maxnorm_u;
__device__ float         g_origss[BATCH];
__device__ float         g_thresh[BATCH];
__device__ unsigned      g_cand_idx  [BATCH * CAP];
__device__ float         g_cand_score[BATCH * CAP];
__device__ float         g_sel_val[BATCH * K_SPARSE];
__device__ int           g_sel_at [BATCH * K_SPARSE];
__device__ int           g_sel_tm [BATCH * K_SPARSE];

// ---------------- K_init: reset per-launch state ----------------
__global__ void k_init() {
    if (threadIdx.x < BATCH) g_cnt[threadIdx.x] = 0u;
    if (threadIdx.x == 4)    g_maxnorm_u = 0u;
}

// ---------------- K0: atom norms (max) + orig sum-of-squares ----------------
__global__ void k0_stats(const float* __restrict__ orig, const float* __restrict__ atoms) {
    __shared__ float red[256];
    int tid = threadIdx.x;
    int bid = blockIdx.x;
    float s = 0.f;
    if (bid < N_ATOMS) {
        const float* a = atoms + (size_t)bid * ATOM_SIZE;
        for (int i = tid; i < ATOM_SIZE; i += 256) { float v = a[i]; s += v * v; }
    } else {
        int b = bid - N_ATOMS;
        const float* o = orig + (size_t)b * N_SAMPLES;
        for (int i = tid; i < N_SAMPLES; i += 256) { float v = o[i]; s += v * v; }
    }
    red[tid] = s; __syncthreads();
    for (int st = 128; st; st >>= 1) { if (tid < st) red[tid] += red[tid + st]; __syncthreads(); }
    if (tid == 0) {
        if (bid < N_ATOMS) atomicMax(&g_maxnorm_u, __float_as_uint(red[0]));
        else               g_origss[bid - N_ATOMS] = red[0];
    }
}

__global__ void k0b_thresh() {
    int b = threadIdx.x;
    if (b < BATCH) {
        float sigma2 = __uint_as_float(g_maxnorm_u) * (g_origss[b] / (float)N_SAMPLES);
        g_thresh[b] = 3.5f * sqrtf(sigma2);
    }
}

// ---------------- K1: convert to bf16 + build padded orig ----------------
__global__ void k1_convert(const float* __restrict__ orig, const float* __restrict__ atoms) {
    int i = blockIdx.x * 256 + threadIdx.x;
    if (i < N_ATOMS * ATOM_SIZE) g_atoms_bf[i] = __float2bfloat16(atoms[i]);
    if (i < BATCH * PADN) {
        int b = i / PADN, p = i - b * PADN;
        int src = p - 512;
        float v = (src >= 0 && src < N_SAMPLES) ? orig[b * N_SAMPLES + src] : 0.f;
        g_origpad_f[i]  = v;
        g_origpad_bf[i] = __float2bfloat16(v);
    }
}

// ---------------- K2: bf16 mma.sync scoring + threshold candidate collection --
// CTA tile: 128 times x 64 atoms, K=1024. 8 warps (4 M x 2 N), warp tile 32x32.
// A = Hankel patch tile built from 8 byte-shifted smem copies of the orig window.
// B = atoms tile, cp.async double-buffered, XOR-16 swizzled for ldmatrix.

#define LDM4(R0,R1,R2,R3,ADDR) \
    asm volatile("ldmatrix.sync.aligned.m8n8.x4.shared.b16 {%0,%1,%2,%3},[%4];" \
                 : "=r"(R0), "=r"(R1), "=r"(R2), "=r"(R3) : "r"(ADDR))

#define MMA16816(D, A, B0, B1) \
    asm volatile("mma.sync.aligned.m16n8k16.row.col.f32.bf16.bf16.f32 " \
                 "{%0,%1,%2,%3},{%4,%5,%6,%7},{%8,%9},{%0,%1,%2,%3};" \
                 : "+f"(D[0]), "+f"(D[1]), "+f"(D[2]), "+f"(D[3]) \
                 : "r"(A[0]), "r"(A[1]), "r"(A[2]), "r"(A[3]), "r"(B0), "r"(B1))

__device__ __forceinline__ void cp_async16(unsigned dst, const void* src) {
    asm volatile("cp.async.ca.shared.global [%0], [%1], 16;" :: "r"(dst), "l"(src));
}

__global__ void __launch_bounds__(256) k2_score() {
    // smem: 8 shifted A-window copies (stride 2320B, 16B aligned, bank-spread),
    //       double-buffered B tile (2 x 64 atoms x 128B), raw window stage.
    __shared__ __align__(16) unsigned char smA[8 * 2320];     // 18560 B
    __shared__ __align__(16) unsigned char smB[2 * 8192];     // 16384 B
    __shared__ __align__(16) __nv_bfloat16 smW[1168];         //  2336 B

    const int b  = blockIdx.z;
    const int t0 = blockIdx.x * 128;
    const int a0 = blockIdx.y * 64;
    const int tid  = threadIdx.x;
    const int lane = tid & 31;
    const int wid  = tid >> 5;
    const int mw = (wid >> 1) * 32;   // warp M offset (time)
    const int nw = (wid & 1) * 32;    // warp N offset (atom)

    // stage orig window (1168 bf16, 16B-aligned source)
    {
        const uint4* s = (const uint4*)(g_origpad_bf + (size_t)b * PADN + t0);
        uint4* d = (uint4*)smW;
        for (int i = tid; i < 146; i += 256) d[i] = s[i];
    }
    __syncthreads();
    // 8 shifted copies: buf_s[j] = w[j+s]
    {
        __nv_bfloat16* A = (__nv_bfloat16*)smA;
        #pragma unroll
        for (int s = 0; s < 8; s++)
            for (int j = tid; j < 1160; j += 256) A[s * 1160 + j] = smW[j + s];
    }

    const unsigned Abase = (unsigned)__cvta_generic_to_shared(smA);
    const unsigned Bbase = (unsigned)__cvta_generic_to_shared(smB);

    // B staging (64 atoms x 64 bf16 per chunk, 16B per cp.async, XOR swizzle)
    auto cpB = [&](int kb) {
        unsigned dstbase = Bbase + (unsigned)((kb & 1) * 8192);
        const char* src0 = (const char*)g_atoms_bf + (size_t)a0 * 2048 + (size_t)kb * 128;
        for (int i = tid; i < 512; i += 256) {
            int n = i >> 3, c = i & 7;
            unsigned dst = dstbase + (unsigned)(n * 128 + ((c * 16) ^ ((n & 7) * 16)));
            cp_async16(dst, src0 + (size_t)n * 2048 + c * 16);
        }
    };

    cpB(0);
    asm volatile("cp.async.commit_group;");

    // lane address bases
    const int q = lane >> 3, lr = lane & 7;
    unsigned aaddr[2];
    #pragma unroll
    for (int mt = 0; mt < 2; mt++)
        aaddr[mt] = Abase + (unsigned)(lr * 2320 + 2 * (mw + mt * 16 + 8 * (q & 1)) + 16 * (q >> 1));
    const int npL   = 8 * ((lane >> 4) & 1) + (lane & 7);
    const unsigned swz   = (unsigned)((lane & 7) * 16);
    const unsigned khalf = (unsigned)(16 * ((lane >> 3) & 1));
    unsigned bn[2];
    bn[0] = (unsigned)((nw + npL) * 128);
    bn[1] = (unsigned)((nw + 16 + npL) * 128);

    float acc[2][4][4];
    #pragma unroll
    for (int mt = 0; mt < 2; mt++)
        #pragma unroll
        for (int nt = 0; nt < 4; nt++)
            #pragma unroll
            for (int c = 0; c < 4; c++) acc[mt][nt][c] = 0.f;

    for (int kb = 0; kb < 16; kb++) {
        if (kb + 1 < 16) {
            cpB(kb + 1);
            asm volatile("cp.async.commit_group;");
            asm volatile("cp.async.wait_group 1;");
        } else {
            asm volatile("cp.async.wait_group 0;");
        }
        __syncthreads();
        const unsigned bufo = (unsigned)((kb & 1) * 8192);
        #pragma unroll
        for (int ksi = 0; ksi < 4; ksi++) {
            const int ks = ksi * 16;
            const int kc = kb * 64 + ks;
            uint32_t afr[2][4];
            LDM4(afr[0][0], afr[0][1], afr[0][2], afr[0][3], aaddr[0] + (unsigned)(2 * kc));
            LDM4(afr[1][0], afr[1][1], afr[1][2], afr[1][3], aaddr[1] + (unsigned)(2 * kc));
            uint32_t bfr[4][2];
            const unsigned koff = ((unsigned)(2 * ks) + khalf) ^ swz;
            LDM4(bfr[0][0], bfr[0][1], bfr[1][0], bfr[1][1], Bbase + bufo + bn[0] + koff);
            LDM4(bfr[2][0], bfr[2][1], bfr[3][0], bfr[3][1], Bbase + bufo + bn[1] + koff);
            #pragma unroll
            for (int mt = 0; mt < 2; mt++)
                #pragma unroll
                for (int nt = 0; nt < 4; nt++)
                    MMA16816(acc[mt][nt], afr[mt], bfr[nt][0], bfr[nt][1]);
        }
        __syncthreads();
    }

    // epilogue: threshold gate -> candidate append
    const float T = g_thresh[b];
    const int g = lane >> 2, t4 = lane & 3;
    #pragma unroll
    for (int mt = 0; mt < 2; mt++)
        #pragma unroll
        for (int nt = 0; nt < 4; nt++)
            #pragma unroll
            for (int ci = 0; ci < 4; ci++) {
                float v = acc[mt][nt][ci];
                if (v > T) {
                    int time = t0 + mw + mt * 16 + g + 8 * (ci >> 1);
                    int atom = a0 + nw + nt * 8 + 2 * t4 + (ci & 1);
                    unsigned pos = atomicAdd(&g_cnt[b], 1u);
                    if (pos < CAP) g_cand_idx[b * CAP + pos] = ((unsigned)atom << 16) | (unsigned)time;
                }
            }
}

// ---------------- K3: exact fp32 re-score of candidates ----------------
__global__ void k3_rescore(const float* __restrict__ atoms) {
    int b = blockIdx.y;
    int warp = blockIdx.x * 8 + (threadIdx.x >> 5);   // grid.x = 64 -> 512 warps
    int lane = threadIdx.x & 31;
    unsigned n = min(g_cnt[b], (unsigned)CAP);
    for (unsigned i = warp; i < n; i += 512) {
        unsigned pk = g_cand_idx[b * CAP + i];
        int atom = (int)(pk >> 16), t = (int)(pk & 0xFFFF);
        const float* op = g_origpad_f + (size_t)b * PADN + t;
        const float* ap = atoms + (size_t)atom * ATOM_SIZE;
        float s = 0.f;
        for (int k = lane; k < ATOM_SIZE; k += 32) s += op[k] * ap[k];
        #pragma unroll
        for (int o = 16; o; o >>= 1) s += __shfl_xor_sync(0xFFFFFFFFu, s, o);
        if (lane == 0) g_cand_score[b * CAP + i] = s;
    }
}

// ---------------- K4: exact top-64 by 64 sequential argmax passes ----------
__global__ void k4_select() {
    int b = blockIdx.x;
    int tid = threadIdx.x;
    unsigned n = min(g_cnt[b], (unsigned)CAP);
    __shared__ float sv[256];
    __shared__ int   si[256];
    float* sc = g_cand_score + (size_t)b * CAP;
    for (int r = 0; r < K_SPARSE; r++) {
        float bv = -1e30f; int bi = -1;
        for (unsigned i = tid; i < n; i += 256) {
            float v = sc[i];
            if (v > bv) { bv = v; bi = (int)i; }
        }
        sv[tid] = bv; si[tid] = bi; __syncthreads();
        for (int st = 128; st; st >>= 1) {
            if (tid < st && sv[tid + st] > sv[tid]) { sv[tid] = sv[tid + st]; si[tid] = si[tid + st]; }
            __syncthreads();
        }
        if (tid == 0) {
            int i = si[0];
            unsigned pk = (i >= 0) ? g_cand_idx[b * CAP + i] : 0u;
            g_sel_val[b * K_SPARSE + r] = (i >= 0) ? sv[0] : 0.f;
            g_sel_at [b * K_SPARSE + r] = (int)(pk >> 16);
            g_sel_tm [b * K_SPARSE + r] = (int)(pk & 0xFFFF);
            if (i >= 0) sc[i] = -1e30f;
        }
        __syncthreads();
    }
}

// ---------------- K5: gather reconstruction ----------------
__global__ void k5_recon(const float* __restrict__ atoms, float* __restrict__ out) {
    int b = blockIdx.y;
    int t = blockIdx.x * 256 + threadIdx.x;
    __shared__ float v[K_SPARSE];
    __shared__ int   at[K_SPARSE], tm[K_SPARSE];
    if (threadIdx.x < K_SPARSE) {
        v [threadIdx.x] = g_sel_val[b * K_SPARSE + threadIdx.x];
        at[threadIdx.x] = g_sel_at [b * K_SPARSE + threadIdx.x];
        tm[threadIdx.x] = g_sel_tm [b * K_SPARSE + threadIdx.x];
    }
    __syncthreads();
    float s = 0.f;
    for (int e = 0; e < K_SPARSE; e++) {
        int d = t - tm[e];
        if ((unsigned)d < (unsigned)ATOM_SIZE) s += atoms[(size_t)at[e] * ATOM_SIZE + d] * v[e];
    }
    out[(size_t)b * N_SAMPLES + t] = s;
}

// ---------------- launch ----------------
extern "C" void kernel_launch(void* const* d_in, const int* in_sizes, int n_in,
                              void* d_out, int out_size) {
    const float* orig  = (const float*)d_in[0];   // [4,1,32768]
    const float* atoms = (const float*)d_in[1];   // [2048,1024]
    float* out = (float*)d_out;                   // [4,1,32768]

    k_init<<<1, 32>>>();
    k0_stats<<<N_ATOMS + BATCH, 256>>>(orig, atoms);
    k0b_thresh<<<1, 32>>>();
    k1_convert<<<(N_ATOMS * ATOM_SIZE) / 256, 256>>>(orig, atoms);
    k2_score<<<dim3(N_SAMPLES / 128, N_ATOMS / 64, BATCH), 256>>>();
    k3_rescore<<<dim3(64, BATCH), 256>>>(atoms);
    k4_select<<<BATCH, 256>>>();
    k5_recon<<<dim3(N_SAMPLES / 256, BATCH), 256>>>(atoms, out);
}